// round 1
// baseline (speedup 1.0000x reference)
#include <cuda_runtime.h>
#include <math.h>

#define Bq 4
#define Nn 500
#define Dd 2048
#define Kk 50
#define H0 28
#define C0 512
#define NP0 (H0*H0)
#define H1 14
#define C1 1024
#define NP1 (H1*H1)
#define IMG 224
#define KS 33
#define RAD 16

// ---------------- device scratch (no allocations allowed) ----------------
__device__ int      g_idx[Bq*Kk];
__device__ unsigned g_min0[Bq*NP0];   // min squared distance, float bits
__device__ unsigned g_min1[Bq*NP1];
__device__ float    g_w[KS];          // normalized gaussian weights
__device__ float    g_comb[Bq*IMG*IMG];
__device__ float    g_tmpH[Bq*IMG*IMG];

// ---------------- init: min buffers to +inf, gaussian weights ----------------
__global__ void init_kernel() {
    int t = blockIdx.x * blockDim.x + threadIdx.x;
    if (t < Bq*NP0) g_min0[t] = 0x7F800000u;      // +inf
    int t1 = t - Bq*NP0;
    if (t1 >= 0 && t1 < Bq*NP1) g_min1[t1] = 0x7F800000u;
    if (blockIdx.x == 0) {
        __shared__ float sw[KS];
        __shared__ float ssum;
        if (threadIdx.x < KS) {
            float x = (float)threadIdx.x - (float)RAD;
            sw[threadIdx.x] = expf(-(x * x) / (2.0f * 4.0f * 4.0f));
        }
        __syncthreads();
        if (threadIdx.x == 0) {
            float s = 0.f;
            for (int i = 0; i < KS; i++) s += sw[i];
            ssum = s;
        }
        __syncthreads();
        if (threadIdx.x < KS) g_w[threadIdx.x] = sw[threadIdx.x] / ssum;
    }
}

// ---------------- top-K over the 2048-d pooled embeddings ----------------
// one block per batch element; exact selection via rank counting
__global__ void topk_kernel(const float* __restrict__ x2,
                            const float* __restrict__ f2,
                            float* __restrict__ out_score) {
    int b = blockIdx.x;
    __shared__ float sd[Nn];
    __shared__ float ssel[Kk];
    int tid = threadIdx.x;
    int lane = tid & 31;
    int w = tid >> 5;                         // 8 warps
    const float4* q = (const float4*)(x2 + (size_t)b * Dd);
    for (int n = w; n < Nn; n += 8) {
        const float4* f = (const float4*)(f2 + (size_t)n * Dd);
        float ss = 0.f;
        #pragma unroll
        for (int j = 0; j < 16; j++) {        // 16*32*4 = 2048 floats
            float4 a = q[lane + j*32];
            float4 c = f[lane + j*32];
            float dx = a.x - c.x, dy = a.y - c.y, dz = a.z - c.z, dw = a.w - c.w;
            ss += dx*dx + dy*dy + dz*dz + dw*dw;
        }
        #pragma unroll
        for (int o = 16; o; o >>= 1) ss += __shfl_xor_sync(0xFFFFFFFFu, ss, o);
        if (lane == 0) sd[n] = ss;
    }
    __syncthreads();
    for (int n = tid; n < Nn; n += 256) {
        float dn = sd[n];
        int r = 0;
        for (int m = 0; m < Nn; m++) {
            float dm = sd[m];
            r += (dm < dn) || (dm == dn && m < n);
        }
        if (r < Kk) { g_idx[b*Kk + r] = n; ssel[r] = sqrtf(dn); }
    }
    __syncthreads();
    if (tid == 0) {
        float s = 0.f;
        for (int i = 0; i < Kk; i++) s += ssel[i];   // deterministic order
        out_score[b] = s / (float)Kk;
    }
}

// ---------------- min-distance map (the HBM-bound part) ----------------
// one warp per (b, pixel, k-chunk); float4-vectorized channel loop;
// atomicMin on float-bits (valid for non-negative floats).
template<int LEVEL, int C, int NP, int KCH>
__global__ void minmap_kernel(const float* __restrict__ x,
                              const float* __restrict__ f) {
    int gw = (blockIdx.x * blockDim.x + threadIdx.x) >> 5;
    int lane = threadIdx.x & 31;
    const int total = Bq * NP * KCH;
    if (gw >= total) return;
    int chunk = gw % KCH;
    int pix   = (gw / KCH) % NP;
    int b     = gw / (KCH * NP);

    constexpr int R = C / 128;                 // float4's per lane
    float4 xr[R];
    const float4* xv = (const float4*)(x + ((size_t)(b * NP + pix)) * C);
    #pragma unroll
    for (int r = 0; r < R; r++) xr[r] = xv[lane + r*32];

    float mn = 3.4e38f;
    for (int k = chunk; k < Kk; k += KCH) {
        int n = g_idx[b*Kk + k];
        const float4* fv = (const float4*)(f + ((size_t)n * NP + pix) * C);
        float ss = 0.f;
        #pragma unroll
        for (int r = 0; r < R; r++) {
            float4 v = fv[lane + r*32];
            float dx = v.x - xr[r].x, dy = v.y - xr[r].y;
            float dz = v.z - xr[r].z, dw = v.w - xr[r].w;
            ss += dx*dx + dy*dy + dz*dz + dw*dw;
        }
        #pragma unroll
        for (int o = 16; o; o >>= 1) ss += __shfl_xor_sync(0xFFFFFFFFu, ss, o);
        mn = fminf(mn, ss);
    }
    if (lane == 0) {
        unsigned* gmin = (LEVEL == 0) ? g_min0 : g_min1;
        atomicMin(gmin + b*NP + pix, __float_as_uint(mn));
    }
}

// ---------------- bilinear upsample (half-pixel centers, edge clamp) ----------------
__device__ __forceinline__ float bil_sample(const unsigned* m, int H, int b, int y, int x) {
    float scale = (float)H / (float)IMG;
    float fy = ((float)y + 0.5f) * scale - 0.5f;
    float fx = ((float)x + 0.5f) * scale - 0.5f;
    float fy0 = floorf(fy), fx0 = floorf(fx);
    float wy = fy - fy0, wx = fx - fx0;
    int y0 = (int)fy0, x0 = (int)fx0;
    int y0c = max(y0, 0), y1c = min(y0 + 1, H - 1);
    int x0c = max(x0, 0), x1c = min(x0 + 1, H - 1);
    const unsigned* p = m + (size_t)b * H * H;
    float v00 = sqrtf(__uint_as_float(p[y0c*H + x0c]));
    float v01 = sqrtf(__uint_as_float(p[y0c*H + x1c]));
    float v10 = sqrtf(__uint_as_float(p[y1c*H + x0c]));
    float v11 = sqrtf(__uint_as_float(p[y1c*H + x1c]));
    return (1.f - wy) * ((1.f - wx)*v00 + wx*v01)
         +        wy  * ((1.f - wx)*v10 + wx*v11);
}

__global__ void resize_kernel() {
    int t = blockIdx.x * blockDim.x + threadIdx.x;
    if (t >= Bq*IMG*IMG) return;
    int x = t % IMG;
    int y = (t / IMG) % IMG;
    int b = t / (IMG * IMG);
    float v0 = bil_sample(g_min0, H0, b, y, x);
    float v1 = bil_sample(g_min1, H1, b, y, x);
    g_comb[t] = 0.5f * (v0 + v1);
}

// ---------------- separable gaussian blur, reflect-101 ----------------
__device__ __forceinline__ int reflect(int i) {
    if (i < 0) return -i;
    if (i > IMG - 1) return 2*(IMG - 1) - i;
    return i;
}

__global__ void blurH_kernel() {
    int t = blockIdx.x * blockDim.x + threadIdx.x;
    if (t >= Bq*IMG*IMG) return;
    int x = t % IMG;
    int row = t / IMG;              // b*IMG + y
    float s = 0.f;
    #pragma unroll
    for (int o = -RAD; o <= RAD; o++) {
        int xx = reflect(x + o);
        s += g_w[o + RAD] * g_comb[row*IMG + xx];
    }
    g_tmpH[t] = s;
}

__global__ void blurV_kernel(float* __restrict__ out_mask) {
    int t = blockIdx.x * blockDim.x + threadIdx.x;
    if (t >= Bq*IMG*IMG) return;
    int x = t % IMG;
    int y = (t / IMG) % IMG;
    int b = t / (IMG * IMG);
    float s = 0.f;
    #pragma unroll
    for (int o = -RAD; o <= RAD; o++) {
        int yy = reflect(y + o);
        s += g_w[o + RAD] * g_tmpH[(b*IMG + yy)*IMG + x];
    }
    out_mask[t] = s;
}

// ---------------- launch ----------------
extern "C" void kernel_launch(void* const* d_in, const int* in_sizes, int n_in,
                              void* d_out, int out_size) {
    const float* x0 = (const float*)d_in[0];
    const float* x1 = (const float*)d_in[1];
    const float* x2 = (const float*)d_in[2];
    const float* f0 = (const float*)d_in[3];
    const float* f1 = (const float*)d_in[4];
    const float* f2 = (const float*)d_in[5];
    float* out = (float*)d_out;           // [0..3] = score, [4..] = mask

    init_kernel<<<16, 256>>>();
    topk_kernel<<<Bq, 256>>>(x2, f2, out);

    // level 0: 4*784 pixels, 2 k-chunks -> 6272 warps
    {
        int warps = Bq * NP0 * 2;
        int blocks = (warps * 32 + 255) / 256;
        minmap_kernel<0, C0, NP0, 2><<<blocks, 256>>>(x0, f0);
    }
    // level 1: 4*196 pixels, 8 k-chunks -> 6272 warps
    {
        int warps = Bq * NP1 * 8;
        int blocks = (warps * 32 + 255) / 256;
        minmap_kernel<1, C1, NP1, 8><<<blocks, 256>>>(x1, f1);
    }

    int npx = Bq * IMG * IMG;
    int blk = (npx + 255) / 256;
    resize_kernel<<<blk, 256>>>();
    blurH_kernel<<<blk, 256>>>();
    blurV_kernel<<<blk, 256>>>(out + 4);
}

// round 2
// speedup vs baseline: 2.3442x; 2.3442x over previous
#include <cuda_runtime.h>
#include <math.h>

#define Bq 4
#define Nn 500
#define Dd 2048
#define Kk 50
#define H0 28
#define C0 512
#define NP0 (H0*H0)
#define H1 14
#define C1 1024
#define NP1 (H1*H1)
#define IMG 224
#define KS 33
#define RAD 16

#define KCH 10          // k-chunks per pixel
#define KPW 5           // k's per warp (KCH*KPW == Kk)
#define BLK0 ((Bq*NP0*KCH)/8)   // 3920 blocks for level 0
#define BLK1 ((Bq*NP1*KCH)/8)   // 980 blocks for level 1

// ---------------- device scratch ----------------
__device__ float    g_d2[Bq*Nn];
__device__ int      g_idx[Bq*Kk];
__device__ unsigned g_min0[Bq*NP0];   // min squared distance, float bits
__device__ unsigned g_min1[Bq*NP1];
__device__ float    g_w[KS];
__device__ float    g_comb[Bq*IMG*IMG];
__device__ float    g_tmpH[Bq*IMG*IMG];

// ---------------- pairwise distances: one warp per (b, n) ----------------
__global__ void dist_kernel(const float* __restrict__ x2,
                            const float* __restrict__ f2) {
    int gw = (blockIdx.x * blockDim.x + threadIdx.x) >> 5;
    int lane = threadIdx.x & 31;
    if (gw >= Bq * Nn) return;
    int b = gw / Nn, n = gw % Nn;
    const float4* q = (const float4*)(x2 + (size_t)b * Dd);
    const float4* f = (const float4*)(f2 + (size_t)n * Dd);
    float ss = 0.f;
    #pragma unroll
    for (int j = 0; j < 16; j++) {          // 16*32*4 = 2048 floats
        float4 a = q[lane + j*32];
        float4 c = f[lane + j*32];
        float dx = a.x - c.x, dy = a.y - c.y, dz = a.z - c.z, dw = a.w - c.w;
        ss += dx*dx + dy*dy + dz*dz + dw*dw;
    }
    #pragma unroll
    for (int o = 16; o; o >>= 1) ss += __shfl_xor_sync(0xFFFFFFFFu, ss, o);
    if (lane == 0) g_d2[gw] = ss;
}

// ---------------- select top-K + score + init scratch ----------------
// one block per batch element; exact selection via rank counting
__global__ void select_kernel(float* __restrict__ out_score) {
    int b = blockIdx.x;
    int tid = threadIdx.x;
    __shared__ float sd[Nn];
    __shared__ float ssel[Kk];

    // init min buffers (this block's batch slice)
    for (int i = tid; i < NP0; i += 256) g_min0[b*NP0 + i] = 0x7F800000u;
    for (int i = tid; i < NP1; i += 256) g_min1[b*NP1 + i] = 0x7F800000u;

    // gaussian weights (block 0 only)
    if (b == 0) {
        __shared__ float sw[KS];
        __shared__ float ssum;
        if (tid < KS) {
            float x = (float)tid - (float)RAD;
            sw[tid] = expf(-(x * x) / (2.0f * 4.0f * 4.0f));
        }
        __syncthreads();
        if (tid == 0) {
            float s = 0.f;
            for (int i = 0; i < KS; i++) s += sw[i];
            ssum = s;
        }
        __syncthreads();
        if (tid < KS) g_w[tid] = sw[tid] / ssum;
    }

    for (int n = tid; n < Nn; n += 256) sd[n] = g_d2[b*Nn + n];
    __syncthreads();
    for (int n = tid; n < Nn; n += 256) {
        float dn = sd[n];
        int r = 0;
        for (int m = 0; m < Nn; m++) {
            float dm = sd[m];
            r += (dm < dn) || (dm == dn && m < n);
        }
        if (r < Kk) { g_idx[b*Kk + r] = n; ssel[r] = sqrtf(fmaxf(dn, 0.f)); }
    }
    __syncthreads();
    if (tid == 0) {
        float s = 0.f;
        for (int i = 0; i < Kk; i++) s += ssel[i];
        out_score[b] = s / (float)Kk;
    }
}

// ---------------- min-distance maps (HBM-bound) ----------------
// One warp handles one (b, pixel, k-range of KPW). Channel dim processed in
// 512-float chunks (4 float4 per lane). KPW independent partial sums keep up
// to 20 loads in flight; all shuffle reductions batched at the end.
template<int C, int NP>
__device__ __forceinline__ void minmap_body(const float* __restrict__ x,
                                            const float* __restrict__ f,
                                            unsigned* __restrict__ gmin,
                                            int wid, int lane) {
    int chunk = wid % KCH;
    int pix   = (wid / KCH) % NP;
    int b     = wid / (KCH * NP);

    int nn[KPW];
    #pragma unroll
    for (int kk = 0; kk < KPW; kk++) nn[kk] = g_idx[b*Kk + chunk*KPW + kk];

    float part[KPW];
    #pragma unroll
    for (int kk = 0; kk < KPW; kk++) part[kk] = 0.f;

    constexpr int NCH = C / 512;
    #pragma unroll
    for (int cc = 0; cc < NCH; cc++) {
        const float4* xv = (const float4*)(x + ((size_t)(b*NP + pix))*C + cc*512);
        float4 xr[4];
        #pragma unroll
        for (int r = 0; r < 4; r++) xr[r] = xv[lane + r*32];
        #pragma unroll
        for (int kk = 0; kk < KPW; kk++) {
            const float4* fv = (const float4*)(f + ((size_t)nn[kk]*NP + pix)*C + cc*512);
            #pragma unroll
            for (int r = 0; r < 4; r++) {
                float4 v = fv[lane + r*32];
                float dx = v.x - xr[r].x, dy = v.y - xr[r].y;
                float dz = v.z - xr[r].z, dw = v.w - xr[r].w;
                part[kk] += dx*dx + dy*dy + dz*dz + dw*dw;
            }
        }
    }
    #pragma unroll
    for (int kk = 0; kk < KPW; kk++) {
        #pragma unroll
        for (int o = 16; o; o >>= 1)
            part[kk] += __shfl_xor_sync(0xFFFFFFFFu, part[kk], o);
    }
    float mn = part[0];
    #pragma unroll
    for (int kk = 1; kk < KPW; kk++) mn = fminf(mn, part[kk]);
    if (lane == 0) atomicMin(gmin + b*NP + pix, __float_as_uint(mn));
}

__global__ void minmap_fused(const float* __restrict__ x0, const float* __restrict__ f0,
                             const float* __restrict__ x1, const float* __restrict__ f1) {
    int lane = threadIdx.x & 31;
    int wIn  = threadIdx.x >> 5;
    if (blockIdx.x < BLK0) {
        int wid = blockIdx.x * 8 + wIn;
        minmap_body<C0, NP0>(x0, f0, g_min0, wid, lane);
    } else {
        int wid = (blockIdx.x - BLK0) * 8 + wIn;
        minmap_body<C1, NP1>(x1, f1, g_min1, wid, lane);
    }
}

// ---------------- bilinear upsample (half-pixel centers, edge clamp) ----------------
__device__ __forceinline__ float bil_sample(const unsigned* m, int H, int b, int y, int x) {
    float scale = (float)H / (float)IMG;
    float fy = ((float)y + 0.5f) * scale - 0.5f;
    float fx = ((float)x + 0.5f) * scale - 0.5f;
    float fy0 = floorf(fy), fx0 = floorf(fx);
    float wy = fy - fy0, wx = fx - fx0;
    int y0 = (int)fy0, x0 = (int)fx0;
    int y0c = max(y0, 0), y1c = min(y0 + 1, H - 1);
    int x0c = max(x0, 0), x1c = min(x0 + 1, H - 1);
    const unsigned* p = m + (size_t)b * H * H;
    float v00 = sqrtf(__uint_as_float(p[y0c*H + x0c]));
    float v01 = sqrtf(__uint_as_float(p[y0c*H + x1c]));
    float v10 = sqrtf(__uint_as_float(p[y1c*H + x0c]));
    float v11 = sqrtf(__uint_as_float(p[y1c*H + x1c]));
    return (1.f - wy) * ((1.f - wx)*v00 + wx*v01)
         +        wy  * ((1.f - wx)*v10 + wx*v11);
}

__global__ void resize_kernel() {
    int t = blockIdx.x * blockDim.x + threadIdx.x;
    if (t >= Bq*IMG*IMG) return;
    int x = t % IMG;
    int y = (t / IMG) % IMG;
    int b = t / (IMG * IMG);
    float v0 = bil_sample(g_min0, H0, b, y, x);
    float v1 = bil_sample(g_min1, H1, b, y, x);
    g_comb[t] = 0.5f * (v0 + v1);
}

// ---------------- separable gaussian blur, reflect-101 ----------------
__device__ __forceinline__ int reflect(int i) {
    if (i < 0) return -i;
    if (i > IMG - 1) return 2*(IMG - 1) - i;
    return i;
}

__global__ void blurH_kernel() {
    int t = blockIdx.x * blockDim.x + threadIdx.x;
    if (t >= Bq*IMG*IMG) return;
    int x = t % IMG;
    int row = t / IMG;              // b*IMG + y
    float s = 0.f;
    #pragma unroll
    for (int o = -RAD; o <= RAD; o++) {
        int xx = reflect(x + o);
        s += g_w[o + RAD] * g_comb[row*IMG + xx];
    }
    g_tmpH[t] = s;
}

__global__ void blurV_kernel(float* __restrict__ out_mask) {
    int t = blockIdx.x * blockDim.x + threadIdx.x;
    if (t >= Bq*IMG*IMG) return;
    int x = t % IMG;
    int y = (t / IMG) % IMG;
    int b = t / (IMG * IMG);
    float s = 0.f;
    #pragma unroll
    for (int o = -RAD; o <= RAD; o++) {
        int yy = reflect(y + o);
        s += g_w[o + RAD] * g_tmpH[(b*IMG + yy)*IMG + x];
    }
    out_mask[t] = s;
}

// ---------------- launch ----------------
extern "C" void kernel_launch(void* const* d_in, const int* in_sizes, int n_in,
                              void* d_out, int out_size) {
    const float* x0 = (const float*)d_in[0];
    const float* x1 = (const float*)d_in[1];
    const float* x2 = (const float*)d_in[2];
    const float* f0 = (const float*)d_in[3];
    const float* f1 = (const float*)d_in[4];
    const float* f2 = (const float*)d_in[5];
    float* out = (float*)d_out;           // [0..3] = score, [4..] = mask

    {   // pairwise distances: Bq*Nn warps
        int warps = Bq * Nn;
        int blocks = (warps * 32 + 255) / 256;
        dist_kernel<<<blocks, 256>>>(x2, f2);
    }
    select_kernel<<<Bq, 256>>>(out);
    minmap_fused<<<BLK0 + BLK1, 256>>>(x0, f0, x1, f1);

    int npx = Bq * IMG * IMG;
    int blk = (npx + 255) / 256;
    resize_kernel<<<blk, 256>>>();
    blurH_kernel<<<blk, 256>>>();
    blurV_kernel<<<blk, 256>>>(out + 4);
}